// round 14
// baseline (speedup 1.0000x reference)
#include <cuda_runtime.h>

// RankDPO loss, B=8192, K=64. Single fused kernel.
// R14 = R11 math, but each warp processes TWO rows (4 independent MUFU chains
// per thread) with __launch_bounds__(256,4) for register headroom -> deeper
// ILP to cover the ~75-cycle LDS->EX2->LG2 dependency chain.
//  * rank: exact f32 strictly-greater counts.
//  * pair loop: packed f32x2 producers on LDS-fed aligned register pairs,
//    scalar consumers; delta >= 0 by monotonicity (no abs); wrapped pair-B via
//    correction accumulator (softplus(-x) = softplus(x) - x).

#define ROWS_PER_BLOCK 16
#define THREADS 256                          // 8 warps x 2 rows each
#define NUM_BLOCKS 512                       // 8192 / 16
#define LOG2E 1.4426950408889634f
#define LN2   0.6931471805599453f
#define FINAL_SCALE (LN2 / 16515072.0f)      // ln2 / (8192 * 2016)

static __device__ float g_partials[NUM_BLOCKS];
static __device__ unsigned int g_ticket = 0;

typedef unsigned long long u64;

static __device__ __forceinline__ float ex2f(float x) {
    float y; asm("ex2.approx.f32 %0, %1;" : "=f"(y) : "f"(x)); return y;
}
static __device__ __forceinline__ float lg2f(float x) {
    float y; asm("lg2.approx.f32 %0, %1;" : "=f"(y) : "f"(x)); return y;
}
static __device__ __forceinline__ u64 packf2(float lo, float hi) {
    u64 r; asm("mov.b64 %0, {%1, %2};" : "=l"(r) : "f"(lo), "f"(hi)); return r;
}
static __device__ __forceinline__ void unpackf2(float& lo, float& hi, u64 v) {
    asm("mov.b64 {%0, %1}, %2;" : "=f"(lo), "=f"(hi) : "l"(v));
}
static __device__ __forceinline__ u64 addx2(u64 a, u64 b) {
    u64 r; asm("add.rn.f32x2 %0, %1, %2;" : "=l"(r) : "l"(a), "l"(b)); return r;
}
static __device__ __forceinline__ u64 mulx2(u64 a, u64 b) {
    u64 r; asm("mul.rn.f32x2 %0, %1, %2;" : "=l"(r) : "l"(a), "l"(b)); return r;
}

__global__ __launch_bounds__(THREADS, 4)
void rankdpo_fused(const float* __restrict__ S,
                   const float* __restrict__ R,
                   float* __restrict__ out) {
    __shared__ __align__(16) float4 Ptab[ROWS_PER_BLOCK][64];
    __shared__ __align__(8)  float2 Qtab[ROWS_PER_BLOCK][64];
    __shared__ __align__(16) float  rsh[ROWS_PER_BLOCK][64];
    __shared__ float wsum[8];
    __shared__ float red[THREADS];
    __shared__ int   isLast;

    const int warp = threadIdx.x >> 5;
    const int lane = threadIdx.x & 31;
    const int rloc0 = warp * 2;              // local row indices
    const int rloc1 = warp * 2 + 1;
    const int row0 = blockIdx.x * ROWS_PER_BLOCK + rloc0;
    const int row1 = row0 + 1;

    // ---- load both rows ----
    const float* s0p = S + row0 * 64;
    const float* r0p = R + row0 * 64;
    const float* s1p = S + row1 * 64;
    const float* r1p = R + row1 * 64;
    const float sa0 = s0p[lane], sa1 = s0p[lane + 32];
    const float ra0 = r0p[lane], ra1 = r0p[lane + 32];
    const float sb0 = s1p[lane], sb1 = s1p[lane + 32];
    const float rb0 = r1p[lane], rb1 = r1p[lane + 32];

    float* rwA = rsh[rloc0];
    float* rwB = rsh[rloc1];
    rwA[lane] = ra0;  rwA[lane + 32] = ra1;
    rwB[lane] = rb0;  rwB[lane + 32] = rb1;
    __syncwarp();

    // ---- rank: exact f32 strictly-greater counts, both rows ----
    int ca0 = 0, ca1 = 0, cb0 = 0, cb1 = 0;
    const float4* rvA = (const float4*)rwA;
    const float4* rvB = (const float4*)rwB;
    #pragma unroll
    for (int q = 0; q < 16; q++) {
        const float4 u = rvA[q];
        ca0 += (u.x > ra0) + (u.y > ra0) + (u.z > ra0) + (u.w > ra0);
        ca1 += (u.x > ra1) + (u.y > ra1) + (u.z > ra1) + (u.w > ra1);
        const float4 v = rvB[q];
        cb0 += (v.x > rb0) + (v.y > rb0) + (v.z > rb0) + (v.w > rb0);
        cb1 += (v.x > rb1) + (v.y > rb1) + (v.z > rb1) + (v.w > rb1);
    }
    const float dA0 = __fdividef(1.f, __logf((float)(ca0 + 2)));
    const float dA1 = __fdividef(1.f, __logf((float)(ca1 + 2)));
    const float dB0 = __fdividef(1.f, __logf((float)(cb0 + 2)));
    const float dB1 = __fdividef(1.f, __logf((float)(cb1 + 2)));
    const float gA0 = 2.f * ra0 - 1.f, gA1 = 2.f * ra1 - 1.f;
    const float gB0 = 2.f * rb0 - 1.f, gB1 = 2.f * rb1 - 1.f;
    const float sLA0 = sa0 * LOG2E, sLA1 = sa1 * LOG2E;
    const float sLB0 = sb0 * LOG2E, sLB1 = sb1 * LOG2E;

    // interleaved tables per row
    Ptab[rloc0][lane]      = make_float4(sLA0, sLA1, gA0, gA1);
    Ptab[rloc0][lane + 32] = make_float4(sLA1, sLA0, gA1, gA0);
    Qtab[rloc0][lane]      = make_float2(dA0, dA1);
    Qtab[rloc0][lane + 32] = make_float2(dA1, dA0);
    Ptab[rloc1][lane]      = make_float4(sLB0, sLB1, gB0, gB1);
    Ptab[rloc1][lane + 32] = make_float4(sLB1, sLB0, gB1, gB0);
    Qtab[rloc1][lane]      = make_float2(dB0, dB1);
    Qtab[rloc1][lane + 32] = make_float2(dB1, dB0);
    __syncwarp();

    const u64 negSA = packf2(-sLA0, -sLA1);
    const u64 negGA = packf2(-gA0, -gA1);
    const u64 negDA = packf2(-dA0, -dA1);
    const u64 negSB = packf2(-sLB0, -sLB1);
    const u64 negGB = packf2(-gB0, -gB1);
    const u64 negDB = packf2(-dB0, -dB1);

    const float4* PbA = &Ptab[rloc0][lane];
    const float2* QbA = &Qtab[rloc0][lane];
    const float4* PbB = &Ptab[rloc1][lane];
    const float2* QbB = &Qtab[rloc1][lane];

    float accA0 = 0.f, accA1 = 0.f, accAC = 0.f;   // row A
    float accB0 = 0.f, accB1 = 0.f, accBC = 0.f;   // row B
    #pragma unroll
    for (int k = 1; k < 32; k++) {
        const bool wrap = (lane + k >= 32);

        // ---- row A ----
        {
            const u64* pv = (const u64*)(PbA + k);
            const u64 sP = pv[0], gP = pv[1];
            const u64 dP = *(const u64*)(QbA + k);
            const u64 x2     = addx2(sP, negSA);
            const u64 delta2 = mulx2(addx2(gP, negGA), addx2(dP, negDA));
            float xA, xB, dtA, dtB;
            unpackf2(xA, xB, x2);
            unpackf2(dtA, dtB, delta2);
            accA0 = fmaf(dtA, lg2f(1.f + ex2f(xA)), accA0);
            accA1 = fmaf(dtB, lg2f(1.f + ex2f(xB)), accA1);
            if (wrap) accAC = fmaf(dtB, xB, accAC);
        }
        // ---- row B ----
        {
            const u64* pv = (const u64*)(PbB + k);
            const u64 sP = pv[0], gP = pv[1];
            const u64 dP = *(const u64*)(QbB + k);
            const u64 x2     = addx2(sP, negSB);
            const u64 delta2 = mulx2(addx2(gP, negGB), addx2(dP, negDB));
            float xA, xB, dtA, dtB;
            unpackf2(xA, xB, x2);
            unpackf2(dtA, dtB, delta2);
            accB0 = fmaf(dtA, lg2f(1.f + ex2f(xA)), accB0);
            accB1 = fmaf(dtB, lg2f(1.f + ex2f(xB)), accB1);
            if (wrap) accBC = fmaf(dtB, xB, accBC);
        }
    }
    {   // gap-32 pairs
        const float deltaA = (gA1 - gA0) * (dA1 - dA0);
        accA0 = fmaf(deltaA, lg2f(1.f + ex2f(sLA1 - sLA0)), accA0);
        const float deltaB = (gB1 - gB0) * (dB1 - dB0);
        accB0 = fmaf(deltaB, lg2f(1.f + ex2f(sLB1 - sLB0)), accB0);
    }
    float acc = (accA0 + accA1 - accAC) + (accB0 + accB1 - accBC);

    // ---- warp reduce ----
    #pragma unroll
    for (int o = 16; o; o >>= 1)
        acc += __shfl_xor_sync(0xffffffffu, acc, o);
    if (lane == 0) wsum[warp] = acc;
    __syncthreads();

    if (threadIdx.x == 0) {
        float s = 0.f;
        #pragma unroll
        for (int w = 0; w < 8; w++) s += wsum[w];
        g_partials[blockIdx.x] = s;
        __threadfence();
        const unsigned tk = atomicAdd(&g_ticket, 1u);
        isLast = (tk == (unsigned)(gridDim.x - 1));
    }
    __syncthreads();

    // ---- last block: deterministic fixed-order reduction of 512 partials ----
    if (isLast) {
        const int tid = threadIdx.x;
        red[tid] = g_partials[tid] + g_partials[tid + 256];
        __syncthreads();
        #pragma unroll
        for (int stride = 128; stride > 0; stride >>= 1) {
            if (tid < stride) red[tid] += red[tid + stride];
            __syncthreads();
        }
        if (tid == 0) {
            out[0] = red[0] * FINAL_SCALE;
            g_ticket = 0;   // reset for graph replay
        }
    }
}

extern "C" void kernel_launch(void* const* d_in, const int* in_sizes, int n_in,
                              void* d_out, int out_size) {
    (void)in_sizes; (void)n_in; (void)out_size;
    const float* s = (const float*)d_in[0];   // policy_logps
    const float* r = (const float*)d_in[1];   // reward_scores
    rankdpo_fused<<<NUM_BLOCKS, THREADS>>>(s, r, (float*)d_out);
}

// round 15
// speedup vs baseline: 1.1212x; 1.1212x over previous
#include <cuda_runtime.h>
#include <cuda_fp16.h>

// RankDPO loss, B=8192, K=64. Single fused kernel.
// R15 = R11 + single-table pair records: ONE LDS.128 per iteration.
//   P[m] = {sL[m], sL[m'], half2(g[m],g[m']), half2(d[m],d[m'])}, m'=(m+32)&63
// delta computed in half2 (values-only f16: R2 precedent, rel_err 2e-4 pass;
// rank compares stay EXACT f32 — R12 showed lossy compares are fatal).
// softplus in lg2 domain; wrapped pair-B via correction accumulator
// (softplus(-x) = softplus(x) - x); delta >= 0 by monotonicity (no abs).

#define ROWS_PER_BLOCK 8
#define THREADS 256
#define NUM_BLOCKS 1024                      // 8192 / 8
#define LOG2E 1.4426950408889634f
#define LN2   0.6931471805599453f
#define FINAL_SCALE (LN2 / 16515072.0f)      // ln2 / (8192 * 2016)

static __device__ float g_partials[NUM_BLOCKS];
static __device__ unsigned int g_ticket = 0;

typedef unsigned long long u64;

static __device__ __forceinline__ float ex2f(float x) {
    float y; asm("ex2.approx.f32 %0, %1;" : "=f"(y) : "f"(x)); return y;
}
static __device__ __forceinline__ float lg2f(float x) {
    float y; asm("lg2.approx.f32 %0, %1;" : "=f"(y) : "f"(x)); return y;
}
static __device__ __forceinline__ u64 packf2(float lo, float hi) {
    u64 r; asm("mov.b64 %0, {%1, %2};" : "=l"(r) : "f"(lo), "f"(hi)); return r;
}
static __device__ __forceinline__ void unpackf2(float& lo, float& hi, u64 v) {
    asm("mov.b64 {%0, %1}, %2;" : "=f"(lo), "=f"(hi) : "l"(v));
}
static __device__ __forceinline__ u64 addx2(u64 a, u64 b) {
    u64 r; asm("add.rn.f32x2 %0, %1, %2;" : "=l"(r) : "l"(a), "l"(b)); return r;
}
// reinterpret float bits <-> half2
static __device__ __forceinline__ float h2f(__half2 h) {
    unsigned u; __builtin_memcpy(&u, &h, 4); return __uint_as_float(u);
}
static __device__ __forceinline__ __half2 f2h2(float f) {
    unsigned u = __float_as_uint(f); __half2 h; __builtin_memcpy(&h, &u, 4); return h;
}

__global__ __launch_bounds__(THREADS, 7)
void rankdpo_fused(const float* __restrict__ S,
                   const float* __restrict__ R,
                   float* __restrict__ out) {
    __shared__ __align__(16) float4 Ptab[ROWS_PER_BLOCK][64];
    __shared__ __align__(16) float  rsh[ROWS_PER_BLOCK][64];
    __shared__ float wsum[ROWS_PER_BLOCK];
    __shared__ float red[THREADS];
    __shared__ int   isLast;

    const int warp = threadIdx.x >> 5;
    const int lane = threadIdx.x & 31;
    const int row  = blockIdx.x * ROWS_PER_BLOCK + warp;

    const float* srow = S + row * 64;
    const float* rrow = R + row * 64;
    const float s0 = srow[lane];
    const float s1 = srow[lane + 32];
    const float r0 = rrow[lane];
    const float r1 = rrow[lane + 32];

    float* rw = rsh[warp];
    rw[lane]      = r0;
    rw[lane + 32] = r1;
    __syncwarp();

    // ---- rank: EXACT f32 strictly-greater counts (ties ~2^-23/pair; tied
    //      pairs have dg=0 -> delta=0, so the dropped tie-break is harmless) --
    int c0 = 0, c1 = 0;
    const float4* rv = (const float4*)rw;
    #pragma unroll
    for (int q = 0; q < 16; q++) {
        const float4 v = rv[q];
        c0 += (v.x > r0) + (v.y > r0) + (v.z > r0) + (v.w > r0);
        c1 += (v.x > r1) + (v.y > r1) + (v.z > r1) + (v.w > r1);
    }
    const float d0 = __fdividef(1.f, __logf((float)(c0 + 2)));
    const float d1 = __fdividef(1.f, __logf((float)(c1 + 2)));
    const float g0 = 2.f * r0 - 1.f;
    const float g1 = 2.f * r1 - 1.f;
    const float sL0 = s0 * LOG2E;   // lg2-domain score
    const float sL1 = s1 * LOG2E;

    // single merged table: one 16B record per entry -> ONE LDS.128 per iter
    const __half2 gd01 = __floats2half2_rn(g0, g1);
    const __half2 dd01 = __floats2half2_rn(d0, d1);
    const __half2 gd10 = __lowhigh2highlow(gd01);
    const __half2 dd10 = __lowhigh2highlow(dd01);
    Ptab[warp][lane]      = make_float4(sL0, sL1, h2f(gd01), h2f(dd01));
    Ptab[warp][lane + 32] = make_float4(sL1, sL0, h2f(gd10), h2f(dd10));
    __syncwarp();

    const u64 negS2 = packf2(-sL0, -sL1);
    const __half2 gOwn = gd01;   // {g0, g1}
    const __half2 dOwn = dd01;   // {d0, d1}

    const float4* Pb = &Ptab[warp][lane];

    float acc0 = 0.f;   // pair-A softplus_lg2 terms
    float acc1 = 0.f;   // pair-B unoriented softplus_lg2 terms
    float accC = 0.f;   // pair-B wrapped correction: sum delta*x (lg2 domain)
    #pragma unroll
    for (int k = 1; k < 32; k++) {
        const float4 A = Pb[k];   // ONE LDS.128: {sL[m], sL[m'], h2(g), h2(d)}

        // packed producer on the naturally-aligned (A.x, A.y) register pair
        const u64 x2 = addx2(packf2(A.x, A.y), negS2);
        float xA, xB;
        unpackf2(xA, xB, x2);

        // delta in half2: (g_m - g_own) * (d_m - d_own), both lanes at once
        const __half2 dg = __hsub2(f2h2(A.z), gOwn);
        const __half2 dd = __hsub2(f2h2(A.w), dOwn);
        const __half2 pr = __hmul2(dg, dd);          // >= 0 by monotonicity
        const float dtA = __low2float(pr);
        const float dtB = __high2float(pr);

        // pair A: partner index lane+k > lane always -> oriented as-is
        acc0 = fmaf(dtA, lg2f(1.f + ex2f(xA)), acc0);

        // pair B: unoriented softplus; wrapped (lane+k>=32 -> partner < own):
        // oriented value = lB - xB, folded via correction accumulator
        acc1 = fmaf(dtB, lg2f(1.f + ex2f(xB)), acc1);
        if (lane + k >= 32) accC = fmaf(dtB, xB, accC);
    }
    {   // gap-32 pair (lane, lane+32): i = lane+32 > j = lane — exact f32
        const float delta = (g1 - g0) * (d1 - d0);   // >= 0
        acc0 = fmaf(delta, lg2f(1.f + ex2f(sL1 - sL0)), acc0);
    }
    float acc = acc0 + acc1 - accC;   // lg2 domain; ln2 folded into FINAL_SCALE

    // ---- warp reduce ----
    #pragma unroll
    for (int o = 16; o; o >>= 1)
        acc += __shfl_xor_sync(0xffffffffu, acc, o);
    if (lane == 0) wsum[warp] = acc;
    __syncthreads();

    if (threadIdx.x == 0) {
        float s = 0.f;
        #pragma unroll
        for (int w = 0; w < ROWS_PER_BLOCK; w++) s += wsum[w];
        g_partials[blockIdx.x] = s;
        __threadfence();
        const unsigned tk = atomicAdd(&g_ticket, 1u);
        isLast = (tk == (unsigned)(gridDim.x - 1));
    }
    __syncthreads();

    // ---- last block: deterministic fixed-order reduction of 1024 partials ----
    if (isLast) {
        const int tid = threadIdx.x;
        float v = g_partials[tid]
                + g_partials[tid + 256]
                + g_partials[tid + 512]
                + g_partials[tid + 768];
        red[tid] = v;
        __syncthreads();
        #pragma unroll
        for (int stride = THREADS / 2; stride > 0; stride >>= 1) {
            if (tid < stride) red[tid] += red[tid + stride];
            __syncthreads();
        }
        if (tid == 0) {
            out[0] = red[0] * FINAL_SCALE;
            g_ticket = 0;   // reset for graph replay
        }
    }
}

extern "C" void kernel_launch(void* const* d_in, const int* in_sizes, int n_in,
                              void* d_out, int out_size) {
    (void)in_sizes; (void)n_in; (void)out_size;
    const float* s = (const float*)d_in[0];   // policy_logps
    const float* r = (const float*)d_in[1];   // reward_scores
    rankdpo_fused<<<NUM_BLOCKS, THREADS>>>(s, r, (float*)d_out);
}